// round 10
// baseline (speedup 1.0000x reference)
#include <cuda_runtime.h>
#include <cstddef>
#include <cstdint>

// Single-pass decoupled-chaining scan for c_t = a_t * c_{t-1} + b_t, c_{-1}=0.
// input  : [B, T, 2*UNITS] fp32   (a = [:,:,:UNITS], b = [:,:,UNITS:])
// output : [B, T, UNITS]
//
// R10 = R9 body + PERSISTENT BLOCKS. R9 ran 8192 blocks in ~18.4 waves;
// T_wave_trans (~2360 cyc ~ 1.3us) x 18 transitions ~ 24us, matching the 22%
// DRAM-idle gap. Now exactly 444 (= 3/SM x 148) blocks grid-stride over the
// 8192 tiles in level-major order: ONE wave, zero transitions. Producer tile
// of tile i is i-256, always in the same or an earlier stride window and all
// blocks are co-resident -> no deadlock. Flags remain consumer-reset
// (graph-replay safe, no prologue kernel).

#define T_C      2048
#define UNITS_C  2048
#define B_MAX    16

constexpr int LANES   = 32;
constexpr int SEGS    = 8;
constexpr int LSEG    = 8;                    // timesteps per thread
constexpr int CHUNK_T = SEGS * LSEG;          // 64
constexpr int CH      = T_C / CHUNK_T;        // 32
constexpr int VG      = UNITS_C / (LANES*4);  // 16 vec-groups per batch row
constexpr int NROWS   = B_MAX * VG * CH;      // 8192 carry rows
constexpr int PERSIST_BLOCKS = 3 * 148;       // 444: one full wave at occ 3

__device__ float4   g_prefix[NROWS][LANES];
__device__ unsigned g_flag  [NROWS][LANES];   // zero-init at load; self-resetting

__device__ __forceinline__ float4 f4_fma(float4 a, float4 x, float4 b)
{   // a*x + b
    float4 r;
    r.x = fmaf(a.x, x.x, b.x); r.y = fmaf(a.y, x.y, b.y);
    r.z = fmaf(a.z, x.z, b.z); r.w = fmaf(a.w, x.w, b.w);
    return r;
}
__device__ __forceinline__ float4 f4_mul(float4 a, float4 b)
{
    float4 r; r.x=a.x*b.x; r.y=a.y*b.y; r.z=a.z*b.z; r.w=a.w*b.w; return r;
}

__global__ void __launch_bounds__(256, 3)
tempo_scan_kernel(const float* __restrict__ in, float* __restrict__ out, int nbatch)
{
    const int lane = threadIdx.x & 31;
    const int seg  = threadIdx.x >> 5;

    const int gpb    = nbatch * VG;        // tiles per chunk level (256 @ B=16)
    const int ntiles = CH * gpb;           // 8192 @ B=16

    constexpr unsigned RS4 = (2 * UNITS_C) / 4;   // input row stride: 1024 f4
    constexpr unsigned OS4 = UNITS_C / 4;         // output row stride: 512 f4

    __shared__ float4 sA[SEGS][LANES];
    __shared__ float4 sC[SEGS][LANES];
    __shared__ float4 sP[LANES];

    // level-major tile order: tile = p*gpb + (g*VG + vg)
    for (int tile = blockIdx.x; tile < ntiles; tile += gridDim.x) {

        const int p  = tile / gpb;             // time chunk (level)
        const int r  = tile % gpb;
        const int g  = r / VG;                 // batch
        const int vg = r % VG;                 // vec-group (32 float4 lanes)

        const int t0 = p * CHUNK_T + seg * LSEG;

        const unsigned ufo = (unsigned)(vg * LANES + lane);
        const unsigned ain = ((unsigned)g * T_C + (unsigned)t0) * RS4 + ufo;
        const unsigned aou = ((unsigned)g * T_C + (unsigned)t0) * OS4 + ufo;

        const float4* pa = (const float4*)in + ain;
        const float4* pb = pa + (UNITS_C / 4);
        float4*       po = (float4*)out + aou;

        // ---- phase 1: issue all loads immediately ----
        float4 A[LSEG], C[LSEG];
        #pragma unroll
        for (int i = 0; i < LSEG; ++i) {
            A[i] = __ldcs(pa + i * RS4);
            C[i] = __ldcs(pb + i * RS4);
        }

        // local scan with zero prefix
        #pragma unroll
        for (int i = 1; i < LSEG; ++i) {
            C[i] = f4_fma(A[i], C[i-1], C[i]);
            A[i] = f4_mul(A[i], A[i-1]);
        }

        sA[seg][lane] = A[LSEG-1];
        sC[seg][lane] = C[LSEG-1];
        __syncthreads();

        // exclusive prefix over segments 0..seg-1
        float4 EA = make_float4(1.f,1.f,1.f,1.f);
        float4 EC = make_float4(0.f,0.f,0.f,0.f);
        #pragma unroll
        for (int j = 0; j < SEGS-1; ++j) {
            if (j < seg) {
                float4 Aj = sA[j][lane], Cj = sC[j][lane];
                EC = f4_fma(Aj, EC, Cj);
                EA = f4_mul(Aj, EA);
            }
        }

        // ---- warp 0: fetch predecessor carry, broadcast via smem ----
        if (seg == 0) {
            float4 P = make_float4(0.f,0.f,0.f,0.f);
            if (p > 0) {
                const int rprev = tile - gpb;       // (p-1, same row)
                unsigned* f = &g_flag[rprev][lane];
                unsigned v;
                asm volatile("ld.global.acquire.gpu.b32 %0, [%1];"
                             : "=r"(v) : "l"(f) : "memory");
                while (!v) {
                    __nanosleep(20);
                    asm volatile("ld.global.acquire.gpu.b32 %0, [%1];"
                                 : "=r"(v) : "l"(f) : "memory");
                }
                P = g_prefix[rprev][lane];
                // consumer-reset for next graph replay (sole consumer)
                asm volatile("st.global.relaxed.gpu.b32 [%0], %1;"
                             :: "l"(f), "r"(0u) : "memory");
            }
            sP[lane] = P;
        }
        __syncthreads();

        const float4 P  = sP[lane];
        const float4 Pc = f4_fma(EA, P, EC);

        // ---- publish own carry FIRST ----
        if (seg == SEGS-1 && p < CH-1) {
            float4 carry = f4_fma(A[LSEG-1], Pc, C[LSEG-1]);
            g_prefix[tile][lane] = carry;
            asm volatile("st.global.release.gpu.b32 [%0], %1;"
                         :: "l"(&g_flag[tile][lane]), "r"(1u) : "memory");
        }

        // ---- finalize + store outputs ----
        #pragma unroll
        for (int i = 0; i < LSEG; ++i) {
            float4 cf = f4_fma(A[i], Pc, C[i]);
            __stcs(po + i * OS4, cf);
        }

        // next iteration's sA/sC writes are ordered after this iteration's
        // sA/sC and sP consumption by the two __syncthreads above plus the
        // sync at the top of the next iteration (first barrier after writes).
        __syncthreads();
    }
}

extern "C" void kernel_launch(void* const* d_in, const int* in_sizes, int n_in,
                              void* d_out, int out_size)
{
    const float* in  = (const float*)d_in[0];
    float*       out = (float*)d_out;

    const int batch  = in_sizes[0] / (T_C * 2 * UNITS_C);
    const int ntiles = CH * batch * VG;

    const int grid = (ntiles < PERSIST_BLOCKS) ? ntiles : PERSIST_BLOCKS;
    tempo_scan_kernel<<<grid, 256>>>(in, out, batch);
}